// round 9
// baseline (speedup 1.0000x reference)
#include <cuda_runtime.h>
#include <cuda_bf16.h>
#include <cstdint>

// ---------------- problem constants ----------------
constexpr int NU   = 4096;
constexpr int NS   = 8192;
constexpr int ND   = 32;
constexpr int NREG = 128;
#define GA_CONST 0.1

// ---------------- tiling ----------------
constexpr int TSB = 512;                 // items per tile (8 warps x 64)
constexpr int TUB = 32;                  // users per tile
constexpr int SBLK = NS / TSB;           // 16 s-strips
constexpr int UBLK = NU / TUB;           // 128 u-blocks
constexpr int NTILE = SBLK * UBLK;       // 2048
constexpr int GRIDN = 444;               // 148 SMs x 3 CTAs: exactly one wave
constexpr int RSUMB = 16;                // blocks 0..15 also do region segment sums
constexpr int REGB  = 128;               // blocks 16..143 also do region loss

// ---------------- device scratch ----------------
__device__ double       g_acc  = 0.0;
__device__ unsigned int g_done = 0u;
__device__ unsigned int g_rsum_done = 0u;
__device__ unsigned int g_tile = 0u;
__device__ float        g_rsum[NREG * ND];
__device__ float        g_rcnt[NREG];

static __device__ __forceinline__ __nv_bfloat162 asbf2(unsigned v) {
    return *reinterpret_cast<__nv_bfloat162*>(&v);
}

__global__ __launch_bounds__(256, 3)
void k_all(const float* __restrict__ user_emb,
           const float* __restrict__ item_emb,
           const int*   __restrict__ mask,
           const float* __restrict__ tq,
           const float* __restrict__ wgt,
           const int*   __restrict__ ridx,
           float*       __restrict__ out)
{
    __shared__ unsigned s_item[TSB * 17];   // ~34.8KB
    __shared__ unsigned s_user[TUB * 16];   // 2KB
    __shared__ float    s_red[8];
    __shared__ double   s_dacc[8];
    __shared__ int      s_tile;
    __shared__ int      s_last;

    const int tid  = threadIdx.x;
    const int b    = blockIdx.x;
    const int warp = tid >> 5, lane = tid & 31;
    double blockpart = 0.0;

    // ============ phase A: auxiliary work on a subset of blocks ============
    if (b < RSUMB) {
        // region segment sums: 256 users per block, warp = 32 users, lane = dim
        const int u0 = b * 256 + warp * 32;
#pragma unroll 4
        for (int k = 0; k < 32; ++k) {
            int u = u0 + k;
            int r = __ldg(ridx + u);
            float e = user_emb[(size_t)u * ND + lane];
            atomicAdd(&g_rsum[r * ND + lane], e);
            if (lane == 0) atomicAdd(&g_rcnt[r], 1.0f);
        }
        __threadfence();
        __syncthreads();
        if (tid == 0) atomicAdd(&g_rsum_done, 1u);
    } else if (b < RSUMB + REGB) {
        // region LOO-deviation: 32 users per block
        if (tid == 0) {
            while (atomicAdd(&g_rsum_done, 0u) < (unsigned)RSUMB) __nanosleep(64);
        }
        __syncthreads();
        __threadfence();

        const int rb = b - RSUMB;                   // 0..127
        const int u0 = rb * 32 + warp * 4;
        double wacc = 0.0;
#pragma unroll
        for (int k = 0; k < 4; ++k) {
            int u = u0 + k;
            int r = ridx[u];
            float cnt = g_rcnt[r];
            float e   = user_emb[(size_t)u * ND + lane];
            float loo = (g_rsum[r * ND + lane] - e) / fmaxf(cnt - 1.0f, 1.0f);
            float dev = fabsf(e - loo);
#pragma unroll
            for (int o = 16; o; o >>= 1) dev += __shfl_xor_sync(0xffffffffu, dev, o);
            if (lane == 0 && cnt > 1.0f) wacc += (double)dev;
        }
        if (lane == 0) s_dacc[warp] = wacc;
        __syncthreads();
        if (tid == 0) {
            double t = 0.0;
#pragma unroll
            for (int i = 0; i < 8; ++i) t += s_dacc[i];
            blockpart = GA_CONST * t;
        }
    }

    // ============ phase B: all blocks steal 512x32 tiles ============
    // tile order: ubase fastest -> consecutive tiles share the item strip
    float lsum = 0.0f;
    int prev_sbase = -1;
    __nv_bfloat162 a0[16], a1[16];
    const int irow = warp * 64 + lane * 2;
    const __nv_bfloat162 zero2 = __floats2bfloat162_rn(0.f, 0.f);

    for (;;) {
        __syncthreads();                            // previous tile fully consumed
        if (tid == 0) s_tile = (int)atomicAdd(&g_tile, 1u);
        __syncthreads();
        const int t = s_tile;
        if (t >= NTILE) break;

        const int sbase = (t >> 7) * TSB;           // slow index
        const int ubase = (t & (UBLK - 1)) * TUB;   // fast index
        const bool newitem = (sbase != prev_sbase);
        prev_sbase = sbase;

        if (newitem) {
            // stage item strip fp32 -> bf16 (16 float4 iters)
            const float4* g = (const float4*)(item_emb + (size_t)sbase * ND);
#pragma unroll
            for (int i = 0; i < 16; ++i) {
                int idx = tid + i * 256;
                float4 v = g[idx];
                int f = idx * 4;
                int row = f >> 5, col = (f & 31) >> 1;
                __nv_bfloat162 h0 = __floats2bfloat162_rn(v.x, v.y);
                __nv_bfloat162 h1 = __floats2bfloat162_rn(v.z, v.w);
                unsigned* p = &s_item[row * 17 + col];
                p[0] = *reinterpret_cast<unsigned*>(&h0);
                p[1] = *reinterpret_cast<unsigned*>(&h1);
            }
        }
        // stage user tile (1 float4 per thread)
        {
            const float4* gu = (const float4*)(user_emb + (size_t)ubase * ND);
            float4 v = gu[tid];
            int f = tid * 4;
            int row = f >> 5, col = (f & 31) >> 1;
            __nv_bfloat162 h0 = __floats2bfloat162_rn(v.x, v.y);
            __nv_bfloat162 h1 = __floats2bfloat162_rn(v.z, v.w);
            unsigned* p = &s_user[row * 16 + col];
            p[0] = *reinterpret_cast<unsigned*>(&h0);
            p[1] = *reinterpret_cast<unsigned*>(&h1);
        }
        __syncthreads();

        if (newitem) {
            const unsigned* r0 = &s_item[irow * 17];
            const unsigned* r1 = r0 + 17;
#pragma unroll
            for (int k = 0; k < 16; ++k) { a0[k] = asbf2(r0[k]); a1[k] = asbf2(r1[k]); }
        }

        const size_t base = (size_t)ubase * NS + sbase + irow;

        int2   mm[2];
        float2 tt[2], ww[2];
        mm[0] = __ldcs((const int2*)  (mask + base));
        tt[0] = __ldcs((const float2*)(tq   + base));
        ww[0] = __ldcs((const float2*)(wgt  + base));

#pragma unroll 4
        for (int u = 0; u < TUB; ++u) {
            const int cur = u & 1, nxt = cur ^ 1;
            if (u + 1 < TUB) {
                const size_t off = base + (size_t)(u + 1) * NS;
                mm[nxt] = __ldcs((const int2*)  (mask + off));
                tt[nxt] = __ldcs((const float2*)(tq   + off));
                ww[nxt] = __ldcs((const float2*)(wgt  + off));
            }
            const uint4* q = (const uint4*)&s_user[u * 16];
            uint4 q0 = q[0], q1 = q[1], q2 = q[2], q3 = q[3];
            unsigned uw[16] = {q0.x,q0.y,q0.z,q0.w, q1.x,q1.y,q1.z,q1.w,
                               q2.x,q2.y,q2.z,q2.w, q3.x,q3.y,q3.z,q3.w};
            __nv_bfloat162 c0a = zero2, c0b = zero2, c1a = zero2, c1b = zero2;
#pragma unroll
            for (int k = 0; k < 16; k += 2) {
                __nv_bfloat162 ua = asbf2(uw[k]);
                __nv_bfloat162 ub = asbf2(uw[k + 1]);
                c0a = __hfma2(a0[k],     ua, c0a);
                c0b = __hfma2(a0[k + 1], ub, c0b);
                c1a = __hfma2(a1[k],     ua, c1a);
                c1b = __hfma2(a1[k + 1], ub, c1b);
            }
            __nv_bfloat162 s0 = __hadd2(c0a, c0b);
            __nv_bfloat162 s1 = __hadd2(c1a, c1b);
            float dot0 = __low2float(s0) + __high2float(s0);
            float dot1 = __low2float(s1) + __high2float(s1);
            float p0 = mm[cur].x ? dot0 : 0.0f;
            float p1 = mm[cur].y ? dot1 : 0.0f;
            float d0 = p0 - tt[cur].x;
            float d1 = p1 - tt[cur].y;
            lsum = fmaf(ww[cur].x * d0, d0, lsum);
            lsum = fmaf(ww[cur].y * d1, d1, lsum);
        }
    }

    // one stream reduction per CTA
#pragma unroll
    for (int o = 16; o; o >>= 1) lsum += __shfl_xor_sync(0xffffffffu, lsum, o);
    if (lane == 0) s_red[warp] = lsum;
    __syncthreads();
    if (tid == 0) {
        float s = 0.0f;
#pragma unroll
        for (int i = 0; i < 8; ++i) s += s_red[i];
        blockpart += (double)s;
    }

    // ============ epilogue: accumulate; last block writes + resets ============
    if (tid == 0) {
        atomicAdd(&g_acc, blockpart);
        __threadfence();
        unsigned old = atomicAdd(&g_done, 1u);
        s_last = (old == (unsigned)(GRIDN - 1));
    }
    __syncthreads();
    if (s_last) {
        for (int i = tid; i < NREG * ND; i += 256) g_rsum[i] = 0.0f;
        if (tid < NREG) g_rcnt[tid] = 0.0f;
        __syncthreads();
        if (tid == 0) {
            __threadfence();
            out[0] = (float)g_acc;
            g_acc  = 0.0;
            g_done = 0u;
            g_rsum_done = 0u;
            g_tile = 0u;
        }
    }
}

// ---------------- launch ----------------
extern "C" void kernel_launch(void* const* d_in, const int* in_sizes, int n_in,
                              void* d_out, int out_size) {
    const float* user_emb = (const float*)d_in[0];
    const float* item_emb = (const float*)d_in[1];
    const int*   mask     = (const int*)  d_in[2];
    const float* tq       = (const float*)d_in[3];
    const float* wgt      = (const float*)d_in[4];
    const int*   ridx     = (const int*)  d_in[5];

    k_all<<<GRIDN, 256>>>(user_emb, item_emb, mask, tq, wgt, ridx, (float*)d_out);
}

// round 10
// speedup vs baseline: 1.3351x; 1.3351x over previous
#include <cuda_runtime.h>
#include <cuda_bf16.h>
#include <cstdint>

// ---------------- problem constants ----------------
constexpr int NU   = 4096;
constexpr int NS   = 8192;
constexpr int ND   = 32;
constexpr int NREG = 128;
#define GA_CONST 0.1

// ---------------- tiling ----------------
constexpr int TSB = 512;                 // items per tile (8 warps x 64)
constexpr int TUB = 32;                  // users per tile
constexpr int SBLK = NS / TSB;           // 16 s-strips
constexpr int UBLK = NU / TUB;           // 128 u-blocks
constexpr int NTILE = SBLK * UBLK;       // 2048
constexpr int GRIDN = 444;               // 148 SMs x 3 CTAs: exactly one wave
constexpr int RSUMB = 16;                // blocks 0..15 also do region segment sums
constexpr int REGB  = 128;               // blocks 16..143 also do region loss

// ---------------- device scratch ----------------
__device__ double       g_acc  = 0.0;
__device__ unsigned int g_done = 0u;
__device__ unsigned int g_rsum_done = 0u;
__device__ unsigned int g_tile = 0u;
__device__ float        g_rsum[NREG * ND];
__device__ float        g_rcnt[NREG];

static __device__ __forceinline__ __nv_bfloat162 asbf2(unsigned v) {
    return *reinterpret_cast<__nv_bfloat162*>(&v);
}

__global__ __launch_bounds__(256, 3)
void k_all(const float* __restrict__ user_emb,
           const float* __restrict__ item_emb,
           const int*   __restrict__ mask,
           const float* __restrict__ tq,
           const float* __restrict__ wgt,
           const int*   __restrict__ ridx,
           float*       __restrict__ out)
{
    __shared__ unsigned s_item[TSB * 17];   // ~34.8KB
    __shared__ unsigned s_user[TUB * 16];   // 2KB
    __shared__ float    s_red[8];
    __shared__ double   s_dacc[8];
    __shared__ int      s_tile;
    __shared__ int      s_last;

    const int tid  = threadIdx.x;
    const int b    = blockIdx.x;
    const int warp = tid >> 5, lane = tid & 31;
    double blockpart = 0.0;

    // ============ phase A: auxiliary work on a subset of blocks ============
    if (b < RSUMB) {
        // region segment sums: 256 users per block, warp = 32 users, lane = dim
        const int u0 = b * 256 + warp * 32;
#pragma unroll 4
        for (int k = 0; k < 32; ++k) {
            int u = u0 + k;
            int r = __ldg(ridx + u);
            float e = user_emb[(size_t)u * ND + lane];
            atomicAdd(&g_rsum[r * ND + lane], e);
            if (lane == 0) atomicAdd(&g_rcnt[r], 1.0f);
        }
        __threadfence();
        __syncthreads();
        if (tid == 0) atomicAdd(&g_rsum_done, 1u);
    } else if (b < RSUMB + REGB) {
        // region LOO-deviation: 32 users per block
        if (tid == 0) {
            while (atomicAdd(&g_rsum_done, 0u) < (unsigned)RSUMB) __nanosleep(64);
        }
        __syncthreads();
        __threadfence();

        const int rb = b - RSUMB;                   // 0..127
        const int u0 = rb * 32 + warp * 4;
        double wacc = 0.0;
#pragma unroll
        for (int k = 0; k < 4; ++k) {
            int u = u0 + k;
            int r = ridx[u];
            float cnt = g_rcnt[r];
            float e   = user_emb[(size_t)u * ND + lane];
            float loo = (g_rsum[r * ND + lane] - e) / fmaxf(cnt - 1.0f, 1.0f);
            float dev = fabsf(e - loo);
#pragma unroll
            for (int o = 16; o; o >>= 1) dev += __shfl_xor_sync(0xffffffffu, dev, o);
            if (lane == 0 && cnt > 1.0f) wacc += (double)dev;
        }
        if (lane == 0) s_dacc[warp] = wacc;
        __syncthreads();
        if (tid == 0) {
            double t = 0.0;
#pragma unroll
            for (int i = 0; i < 8; ++i) t += s_dacc[i];
            blockpart = GA_CONST * t;
        }
    }

    // ============ phase B: all blocks steal 512x32 tiles ============
    // tile order: sbase FASTEST (full column-window spread across concurrent CTAs;
    // consecutive stolen tiles share ubase -> skip user staging when unchanged)
    float lsum = 0.0f;
    int prev_ubase = -1;
    const int irow = warp * 64 + lane * 2;
    const __nv_bfloat162 zero2 = __floats2bfloat162_rn(0.f, 0.f);

    for (;;) {
        __syncthreads();                            // previous tile fully consumed
        if (tid == 0) s_tile = (int)atomicAdd(&g_tile, 1u);
        __syncthreads();
        const int t = s_tile;
        if (t >= NTILE) break;

        const int sbase = (t & (SBLK - 1)) * TSB;   // fast index
        const int ubase = (t >> 4) * TUB;           // slow index

        // stage item strip fp32 -> bf16 (16 float4 iters)
        {
            const float4* g = (const float4*)(item_emb + (size_t)sbase * ND);
#pragma unroll
            for (int i = 0; i < 16; ++i) {
                int idx = tid + i * 256;
                float4 v = g[idx];
                int f = idx * 4;
                int row = f >> 5, col = (f & 31) >> 1;
                __nv_bfloat162 h0 = __floats2bfloat162_rn(v.x, v.y);
                __nv_bfloat162 h1 = __floats2bfloat162_rn(v.z, v.w);
                unsigned* p = &s_item[row * 17 + col];
                p[0] = *reinterpret_cast<unsigned*>(&h0);
                p[1] = *reinterpret_cast<unsigned*>(&h1);
            }
        }
        // stage user tile only when ubase changes
        if (ubase != prev_ubase) {
            const float4* gu = (const float4*)(user_emb + (size_t)ubase * ND);
            float4 v = gu[tid];
            int f = tid * 4;
            int row = f >> 5, col = (f & 31) >> 1;
            __nv_bfloat162 h0 = __floats2bfloat162_rn(v.x, v.y);
            __nv_bfloat162 h1 = __floats2bfloat162_rn(v.z, v.w);
            unsigned* p = &s_user[row * 16 + col];
            p[0] = *reinterpret_cast<unsigned*>(&h0);
            p[1] = *reinterpret_cast<unsigned*>(&h1);
        }
        prev_ubase = ubase;
        __syncthreads();

        // item fragments: 2 rows per lane
        __nv_bfloat162 a0[16], a1[16];
        {
            const unsigned* r0 = &s_item[irow * 17];
            const unsigned* r1 = r0 + 17;
#pragma unroll
            for (int k = 0; k < 16; ++k) { a0[k] = asbf2(r0[k]); a1[k] = asbf2(r1[k]); }
        }

        const size_t base = (size_t)ubase * NS + sbase + irow;

        int2   mm[2];
        float2 tt[2], ww[2];
        mm[0] = __ldcs((const int2*)  (mask + base));
        tt[0] = __ldcs((const float2*)(tq   + base));
        ww[0] = __ldcs((const float2*)(wgt  + base));

#pragma unroll 4
        for (int u = 0; u < TUB; ++u) {
            const int cur = u & 1, nxt = cur ^ 1;
            if (u + 1 < TUB) {
                const size_t off = base + (size_t)(u + 1) * NS;
                mm[nxt] = __ldcs((const int2*)  (mask + off));
                tt[nxt] = __ldcs((const float2*)(tq   + off));
                ww[nxt] = __ldcs((const float2*)(wgt  + off));
            }
            const uint4* q = (const uint4*)&s_user[u * 16];
            uint4 q0 = q[0], q1 = q[1], q2 = q[2], q3 = q[3];
            unsigned uw[16] = {q0.x,q0.y,q0.z,q0.w, q1.x,q1.y,q1.z,q1.w,
                               q2.x,q2.y,q2.z,q2.w, q3.x,q3.y,q3.z,q3.w};
            __nv_bfloat162 c0a = zero2, c0b = zero2, c1a = zero2, c1b = zero2;
#pragma unroll
            for (int k = 0; k < 16; k += 2) {
                __nv_bfloat162 ua = asbf2(uw[k]);
                __nv_bfloat162 ub = asbf2(uw[k + 1]);
                c0a = __hfma2(a0[k],     ua, c0a);
                c0b = __hfma2(a0[k + 1], ub, c0b);
                c1a = __hfma2(a1[k],     ua, c1a);
                c1b = __hfma2(a1[k + 1], ub, c1b);
            }
            __nv_bfloat162 s0 = __hadd2(c0a, c0b);
            __nv_bfloat162 s1 = __hadd2(c1a, c1b);
            float dot0 = __low2float(s0) + __high2float(s0);
            float dot1 = __low2float(s1) + __high2float(s1);
            float p0 = mm[cur].x ? dot0 : 0.0f;
            float p1 = mm[cur].y ? dot1 : 0.0f;
            float d0 = p0 - tt[cur].x;
            float d1 = p1 - tt[cur].y;
            lsum = fmaf(ww[cur].x * d0, d0, lsum);
            lsum = fmaf(ww[cur].y * d1, d1, lsum);
        }
    }

    // one stream reduction per CTA
#pragma unroll
    for (int o = 16; o; o >>= 1) lsum += __shfl_xor_sync(0xffffffffu, lsum, o);
    if (lane == 0) s_red[warp] = lsum;
    __syncthreads();
    if (tid == 0) {
        float s = 0.0f;
#pragma unroll
        for (int i = 0; i < 8; ++i) s += s_red[i];
        blockpart += (double)s;
    }

    // ============ epilogue: accumulate; last block writes + resets ============
    if (tid == 0) {
        atomicAdd(&g_acc, blockpart);
        __threadfence();
        unsigned old = atomicAdd(&g_done, 1u);
        s_last = (old == (unsigned)(GRIDN - 1));
    }
    __syncthreads();
    if (s_last) {
        for (int i = tid; i < NREG * ND; i += 256) g_rsum[i] = 0.0f;
        if (tid < NREG) g_rcnt[tid] = 0.0f;
        __syncthreads();
        if (tid == 0) {
            __threadfence();
            out[0] = (float)g_acc;
            g_acc  = 0.0;
            g_done = 0u;
            g_rsum_done = 0u;
            g_tile = 0u;
        }
    }
}

// ---------------- launch ----------------
extern "C" void kernel_launch(void* const* d_in, const int* in_sizes, int n_in,
                              void* d_out, int out_size) {
    const float* user_emb = (const float*)d_in[0];
    const float* item_emb = (const float*)d_in[1];
    const int*   mask     = (const int*)  d_in[2];
    const float* tq       = (const float*)d_in[3];
    const float* wgt      = (const float*)d_in[4];
    const int*   ridx     = (const int*)  d_in[5];

    k_all<<<GRIDN, 256>>>(user_emb, item_emb, mask, tq, wgt, ridx, (float*)d_out);
}